// round 2
// baseline (speedup 1.0000x reference)
#include <cuda_runtime.h>
#include <cuda_bf16.h>
#include <math.h>

// Problem dims
#define BATCH 64
#define SEQ   256
#define DIM   384
#define NHEAD 6
#define HDIM  64
#define NTOK  (BATCH * SEQ)      // 16384
#define FFDIM (4 * DIM)          // 1536

// ---------------- scratch (static device globals; no allocation) -------------
__device__ float g_h  [NTOK * DIM];    // LN output (reused for LN1 and LN2)
__device__ float g_q  [NTOK * DIM];
__device__ float g_k  [NTOK * DIM];
__device__ float g_v  [NTOK * DIM];
__device__ float g_ctx[NTOK * DIM];
__device__ float g_x1 [NTOK * DIM];    // x + attn out
__device__ float g_ff [NTOK * FFDIM];  // FFN hidden

// ---------------- LayerNorm: one warp per token ------------------------------
__global__ void ln_kernel(const float* __restrict__ x,
                          const float* __restrict__ g,
                          const float* __restrict__ be,
                          float* __restrict__ out)
{
    int warp = (blockIdx.x * blockDim.x + threadIdx.x) >> 5;
    int lane = threadIdx.x & 31;
    if (warp >= NTOK) return;
    const float* row = x + (size_t)warp * DIM;
    float v[12];
    float s = 0.f, ss = 0.f;
#pragma unroll
    for (int i = 0; i < 12; i++) {
        v[i] = row[lane + 32 * i];
        s  += v[i];
        ss += v[i] * v[i];
    }
#pragma unroll
    for (int o = 16; o; o >>= 1) {
        s  += __shfl_xor_sync(0xffffffffu, s, o);
        ss += __shfl_xor_sync(0xffffffffu, ss, o);
    }
    float mean = s * (1.0f / DIM);
    float var  = ss * (1.0f / DIM) - mean * mean;
    float rstd = rsqrtf(var + 1e-5f);
    float* orow = out + (size_t)warp * DIM;
#pragma unroll
    for (int i = 0; i < 12; i++) {
        int c = lane + 32 * i;
        orow[c] = (v[i] - mean) * rstd * g[c] + be[c];
    }
}

// ---------------- Generic tiled SGEMM: C = act(A@W + bias + resid) -----------
// A: [N,K] row-major, W: [K,M] row-major, C: [N,M].
// BM=BN=64, BK=16, 256 threads, 4x4 register microtile per thread.
template<bool RELU, bool BIAS, bool RESID>
__global__ void __launch_bounds__(256)
gemm_kernel(const float* __restrict__ A, const float* __restrict__ W,
            const float* __restrict__ bias, const float* __restrict__ resid,
            float* __restrict__ C, int N, int K, int M)
{
    __shared__ float As[16][64];   // [k][row]
    __shared__ float Ws[16][64];   // [k][col]

    int tid = threadIdx.x;
    int tx = tid & 15;             // col group
    int ty = tid >> 4;             // row group
    int row0 = blockIdx.x * 64;
    int col0 = blockIdx.y * 64;

    // load mappings
    int aRow = tid >> 2;           // 0..63
    int aK4  = (tid & 3) * 4;      // 0,4,8,12
    int wK   = tid >> 4;           // 0..15
    int wC4  = (tid & 15) * 4;     // 0..60

    float acc[4][4] = {{0.f}};

    for (int k0 = 0; k0 < K; k0 += 16) {
        float4 av = *(const float4*)&A[(size_t)(row0 + aRow) * K + k0 + aK4];
        As[aK4 + 0][aRow] = av.x;
        As[aK4 + 1][aRow] = av.y;
        As[aK4 + 2][aRow] = av.z;
        As[aK4 + 3][aRow] = av.w;
        float4 wv = *(const float4*)&W[(size_t)(k0 + wK) * M + col0 + wC4];
        *(float4*)&Ws[wK][wC4] = wv;
        __syncthreads();
#pragma unroll
        for (int kk = 0; kk < 16; kk++) {
            float4 a = *(float4*)&As[kk][ty * 4];
            float4 b = *(float4*)&Ws[kk][tx * 4];
            acc[0][0] += a.x * b.x; acc[0][1] += a.x * b.y; acc[0][2] += a.x * b.z; acc[0][3] += a.x * b.w;
            acc[1][0] += a.y * b.x; acc[1][1] += a.y * b.y; acc[1][2] += a.y * b.z; acc[1][3] += a.y * b.w;
            acc[2][0] += a.z * b.x; acc[2][1] += a.z * b.y; acc[2][2] += a.z * b.z; acc[2][3] += a.z * b.w;
            acc[3][0] += a.w * b.x; acc[3][1] += a.w * b.y; acc[3][2] += a.w * b.z; acc[3][3] += a.w * b.w;
        }
        __syncthreads();
    }

    float4 bv = make_float4(0.f, 0.f, 0.f, 0.f);
    if (BIAS) bv = *(const float4*)&bias[col0 + tx * 4];
#pragma unroll
    for (int i = 0; i < 4; i++) {
        int r = row0 + ty * 4 + i;
        float4 val;
        val.x = acc[i][0] + bv.x;
        val.y = acc[i][1] + bv.y;
        val.z = acc[i][2] + bv.z;
        val.w = acc[i][3] + bv.w;
        if (RESID) {
            float4 rv = *(const float4*)&resid[(size_t)r * M + col0 + tx * 4];
            val.x += rv.x; val.y += rv.y; val.z += rv.z; val.w += rv.w;
        }
        if (RELU) {
            val.x = fmaxf(val.x, 0.f); val.y = fmaxf(val.y, 0.f);
            val.z = fmaxf(val.z, 0.f); val.w = fmaxf(val.w, 0.f);
        }
        *(float4*)&C[(size_t)r * M + col0 + tx * 4] = val;
    }
}

// ---------------- Causal flash attention -------------------------------------
// Grid: (S/64, H, B), 256 threads. q/k/v layout: [b, s, h, hd] = [NTOK, DIM].
// Per block: 64 queries x HDIM=64, online softmax over key tiles of 64.
__global__ void __launch_bounds__(256)
attn_kernel(const float* __restrict__ q, const float* __restrict__ k,
            const float* __restrict__ v, float* __restrict__ ctx)
{
    extern __shared__ float sm[];
    float* Qst   = sm;                 // [64][64] d-major: Qst[d*64 + qrow]
    float* Kst   = Qst + 64 * 64;      // [64][64] d-major: Kst[d*64 + kcol]
    float* Vs    = Kst + 64 * 64;      // [64][64] Vs[k*64 + hd]
    float* Ss    = Vs + 64 * 64;       // [64][65]
    float* alphas = Ss + 64 * 65;      // [64]
    float* m_s   = alphas + 64;        // [64]
    float* l_s   = m_s + 64;           // [64]

    int qt = blockIdx.x;
    int h  = blockIdx.y;
    int b  = blockIdx.z;
    int tid = threadIdx.x;
    int tx = tid & 15, ty = tid >> 4;

    const float* qbase = q + (size_t)b * SEQ * DIM + h * HDIM;
    const float* kbase = k + (size_t)b * SEQ * DIM + h * HDIM;
    const float* vbase = v + (size_t)b * SEQ * DIM + h * HDIM;

    // Load Q tile, transposed to d-major
#pragma unroll
    for (int i = 0; i < 4; i++) {
        int f = tid + i * 256;            // float4 index in [0,1024)
        int r = f >> 4, d4 = (f & 15) << 2;
        float4 val = *(const float4*)&qbase[(size_t)(qt * 64 + r) * DIM + d4];
        Qst[(d4 + 0) * 64 + r] = val.x;
        Qst[(d4 + 1) * 64 + r] = val.y;
        Qst[(d4 + 2) * 64 + r] = val.z;
        Qst[(d4 + 3) * 64 + r] = val.w;
    }
    if (tid < 64) { m_s[tid] = -1e30f; l_s[tid] = 0.f; }

    float o[4][4] = {{0.f}};

    for (int kt = 0; kt <= qt; kt++) {
        __syncthreads();   // covers Q/stat init (iter 0) and protects Kst/Vs reuse
        // Load K tile transposed
#pragma unroll
        for (int i = 0; i < 4; i++) {
            int f = tid + i * 256;
            int r = f >> 4, d4 = (f & 15) << 2;
            float4 val = *(const float4*)&kbase[(size_t)(kt * 64 + r) * DIM + d4];
            Kst[(d4 + 0) * 64 + r] = val.x;
            Kst[(d4 + 1) * 64 + r] = val.y;
            Kst[(d4 + 2) * 64 + r] = val.z;
            Kst[(d4 + 3) * 64 + r] = val.w;
        }
        __syncthreads();

        // S tile = Q @ K^T (microtile 4x4)
        float s_[4][4] = {{0.f}};
#pragma unroll
        for (int d = 0; d < 64; d++) {
            float4 a  = *(float4*)&Qst[d * 64 + ty * 4];
            float4 bq = *(float4*)&Kst[d * 64 + tx * 4];
            s_[0][0] += a.x * bq.x; s_[0][1] += a.x * bq.y; s_[0][2] += a.x * bq.z; s_[0][3] += a.x * bq.w;
            s_[1][0] += a.y * bq.x; s_[1][1] += a.y * bq.y; s_[1][2] += a.y * bq.z; s_[1][3] += a.y * bq.w;
            s_[2][0] += a.z * bq.x; s_[2][1] += a.z * bq.y; s_[2][2] += a.z * bq.z; s_[2][3] += a.z * bq.w;
            s_[3][0] += a.w * bq.x; s_[3][1] += a.w * bq.y; s_[3][2] += a.w * bq.z; s_[3][3] += a.w * bq.w;
        }
        // scale + causal mask + store
#pragma unroll
        for (int i = 0; i < 4; i++) {
#pragma unroll
            for (int j = 0; j < 4; j++) {
                int qi = ty * 4 + i, kj = tx * 4 + j;
                float val = s_[i][j] * 0.125f;   // 1/sqrt(64)
                if (kt * 64 + kj > qt * 64 + qi) val = -1e30f;
                Ss[qi * 65 + kj] = val;
            }
        }
        __syncthreads();

        // Load V tile (independent smem region) while 64 threads do softmax
#pragma unroll
        for (int i = 0; i < 4; i++) {
            int f = tid + i * 256;
            int r = f >> 4, d4 = (f & 15) << 2;
            float4 val = *(const float4*)&vbase[(size_t)(kt * 64 + r) * DIM + d4];
            *(float4*)&Vs[r * 64 + d4] = val;
        }
        if (tid < 64) {
            float m_old = m_s[tid];
            float mt = m_old;
#pragma unroll 8
            for (int c = 0; c < 64; c++) mt = fmaxf(mt, Ss[tid * 65 + c]);
            float alpha = __expf(m_old - mt);
            float sum = 0.f;
#pragma unroll 8
            for (int c = 0; c < 64; c++) {
                float p = __expf(Ss[tid * 65 + c] - mt);
                Ss[tid * 65 + c] = p;
                sum += p;
            }
            m_s[tid] = mt;
            l_s[tid] = l_s[tid] * alpha + sum;
            alphas[tid] = alpha;
        }
        __syncthreads();

        // rescale accumulators
#pragma unroll
        for (int i = 0; i < 4; i++) {
            float al = alphas[ty * 4 + i];
            o[i][0] *= al; o[i][1] *= al; o[i][2] *= al; o[i][3] *= al;
        }
        // O += P @ V
#pragma unroll
        for (int kk = 0; kk < 64; kk++) {
            float4 bv = *(float4*)&Vs[kk * 64 + tx * 4];
            float a0 = Ss[(ty * 4 + 0) * 65 + kk];
            float a1 = Ss[(ty * 4 + 1) * 65 + kk];
            float a2 = Ss[(ty * 4 + 2) * 65 + kk];
            float a3 = Ss[(ty * 4 + 3) * 65 + kk];
            o[0][0] += a0 * bv.x; o[0][1] += a0 * bv.y; o[0][2] += a0 * bv.z; o[0][3] += a0 * bv.w;
            o[1][0] += a1 * bv.x; o[1][1] += a1 * bv.y; o[1][2] += a1 * bv.z; o[1][3] += a1 * bv.w;
            o[2][0] += a2 * bv.x; o[2][1] += a2 * bv.y; o[2][2] += a2 * bv.z; o[2][3] += a2 * bv.w;
            o[3][0] += a3 * bv.x; o[3][1] += a3 * bv.y; o[3][2] += a3 * bv.z; o[3][3] += a3 * bv.w;
        }
    }

    // write ctx = O / l
    float* obase = ctx + (size_t)b * SEQ * DIM + h * HDIM;
#pragma unroll
    for (int i = 0; i < 4; i++) {
        int qi = ty * 4 + i;
        float inv_l = 1.0f / l_s[qi];
        float4 val;
        val.x = o[i][0] * inv_l;
        val.y = o[i][1] * inv_l;
        val.z = o[i][2] * inv_l;
        val.w = o[i][3] * inv_l;
        *(float4*)&obase[(size_t)(qt * 64 + qi) * DIM + tx * 4] = val;
    }
}

// ---------------- launch ------------------------------------------------------
static float* dev_ptr(const void* sym)
{
    void* p = nullptr;
    cudaGetSymbolAddress(&p, sym);
    return (float*)p;
}

extern "C" void kernel_launch(void* const* d_in, const int* in_sizes, int n_in,
                              void* d_out, int out_size)
{
    (void)in_sizes; (void)n_in; (void)out_size;
    const float* x   = (const float*)d_in[0];
    const float* wq  = (const float*)d_in[1];
    const float* wk  = (const float*)d_in[2];
    const float* wv  = (const float*)d_in[3];
    const float* wo  = (const float*)d_in[4];
    const float* bo  = (const float*)d_in[5];
    const float* w1  = (const float*)d_in[6];
    const float* b1  = (const float*)d_in[7];
    const float* w2  = (const float*)d_in[8];
    const float* b2  = (const float*)d_in[9];
    const float* g1  = (const float*)d_in[10];
    const float* be1 = (const float*)d_in[11];
    const float* g2  = (const float*)d_in[12];
    const float* be2 = (const float*)d_in[13];
    float* out = (float*)d_out;

    float* h   = dev_ptr(g_h);
    float* qb  = dev_ptr(g_q);
    float* kb  = dev_ptr(g_k);
    float* vb  = dev_ptr(g_v);
    float* ctx = dev_ptr(g_ctx);
    float* x1  = dev_ptr(g_x1);
    float* ff  = dev_ptr(g_ff);

    const int ATTN_SMEM = (64 * 64 * 3 + 64 * 65 + 64 * 3) * sizeof(float); // 66560
    cudaFuncSetAttribute(attn_kernel, cudaFuncAttributeMaxDynamicSharedMemorySize, ATTN_SMEM);

    dim3 gemmGridD(NTOK / 64, DIM / 64);    // 256 x 6
    dim3 gemmGridF(NTOK / 64, FFDIM / 64);  // 256 x 24

    // LN1
    ln_kernel<<<NTOK / 8, 256>>>(x, g1, be1, h);
    // QKV projections
    gemm_kernel<false, false, false><<<gemmGridD, 256>>>(h, wq, nullptr, nullptr, qb, NTOK, DIM, DIM);
    gemm_kernel<false, false, false><<<gemmGridD, 256>>>(h, wk, nullptr, nullptr, kb, NTOK, DIM, DIM);
    gemm_kernel<false, false, false><<<gemmGridD, 256>>>(h, wv, nullptr, nullptr, vb, NTOK, DIM, DIM);
    // attention
    attn_kernel<<<dim3(SEQ / 64, NHEAD, BATCH), 256, ATTN_SMEM>>>(qb, kb, vb, ctx);
    // output projection + residual
    gemm_kernel<false, true, true><<<gemmGridD, 256>>>(ctx, wo, bo, x, x1, NTOK, DIM, DIM);
    // LN2
    ln_kernel<<<NTOK / 8, 256>>>(x1, g2, be2, h);
    // FFN
    gemm_kernel<true, true, false><<<gemmGridF, 256>>>(h, w1, b1, nullptr, ff, NTOK, DIM, FFDIM);
    gemm_kernel<false, true, true><<<gemmGridD, 256>>>(ff, w2, b2, x1, out, NTOK, FFDIM, DIM);
}

// round 4
// speedup vs baseline: 1.2432x; 1.2432x over previous
#include <cuda_runtime.h>
#include <cuda_bf16.h>
#include <cstdint>
#include <math.h>

// Problem dims
#define BATCH 64
#define SEQ   256
#define DIM   384
#define NHEAD 6
#define HDIM  64
#define NTOK  (BATCH * SEQ)      // 16384
#define FFDIM (4 * DIM)          // 1536

// ---------------- scratch (static device globals; no allocation) -------------
__device__ float g_h  [NTOK * DIM];
__device__ float g_q  [NTOK * DIM];
__device__ float g_k  [NTOK * DIM];
__device__ float g_v  [NTOK * DIM];
__device__ float g_ctx[NTOK * DIM];
__device__ float g_x1 [NTOK * DIM];
__device__ float g_ff [NTOK * FFDIM];

// ---------------- helpers -----------------------------------------------------
__device__ __forceinline__ uint32_t f2tf32(float x) {
    uint32_t r;
    asm("cvt.rna.tf32.f32 %0, %1;" : "=r"(r) : "f"(x));
    return r;
}

__device__ __forceinline__ void mma_tf32(float* c, const uint32_t* a, const uint32_t* b) {
    asm volatile(
        "mma.sync.aligned.m16n8k8.row.col.f32.tf32.tf32.f32 "
        "{%0,%1,%2,%3}, {%4,%5,%6,%7}, {%8,%9}, {%0,%1,%2,%3};"
        : "+f"(c[0]), "+f"(c[1]), "+f"(c[2]), "+f"(c[3])
        : "r"(a[0]), "r"(a[1]), "r"(a[2]), "r"(a[3]), "r"(b[0]), "r"(b[1]));
}

// ================= tf32 mma.sync GEMM: C = act(A@W + bias + resid) ============
// A: [N,K] row-major fp32, W: [K,M] row-major fp32, C: [N,M].
// CTA tile 128x64, BK=32, 8 warps (2x4), warp tile 64x16 (4x2 m16n8k8 tiles).
// smem holds tf32 values pre-permuted into mma fragment order:
//   sA[st][(kc*8 + mb)*128 + lane*4 + f]   (kc: k8-chunk 0..3, mb: 16-row tile 0..7)
//   sB[st][(kc*8 + nb)*64  + lane*2 + f]   (nb: 8-col tile 0..7)
// A frag (m16n8k8): a_f at row = g + 8*(f&1), col = t + 4*(f>>1); g=lane>>2, t=lane&3
// B frag:           b_f at k   = t + 4*f,     n  = g
template<bool RELU, bool BIAS, bool RESID>
__global__ void __launch_bounds__(256)
mma_gemm_kernel(const float* __restrict__ A, const float* __restrict__ W,
                const float* __restrict__ bias, const float* __restrict__ resid,
                float* __restrict__ C, int K, int M)
{
    __shared__ uint32_t sA[2][4096];   // 2 x 16KB
    __shared__ uint32_t sB[2][2048];   // 2 x 8KB

    const int tid  = threadIdx.x;
    const int wid  = tid >> 5;
    const int lane = tid & 31;
    const int warpM = wid & 1;         // 0..1 (64 rows each)
    const int warpN = wid >> 1;        // 0..3 (16 cols each)
    const int row0 = blockIdx.x * 128;
    const int col0 = blockIdx.y * 64;

    float acc[4][2][4];
#pragma unroll
    for (int mt = 0; mt < 4; mt++)
#pragma unroll
        for (int nt = 0; nt < 2; nt++)
#pragma unroll
            for (int f = 0; f < 4; f++) acc[mt][nt][f] = 0.f;

    const int KT = K >> 5;

    float4 ra[4];
    float4 rb[2];

    // ---- LDG helpers (indices are compile-time derivable from tid) ----
    auto ldg_tile = [&](int kt) {
        const int k0 = kt << 5;
#pragma unroll
        for (int i = 0; i < 4; i++) {
            int f4 = tid + i * 256;             // [0,1024)
            int r = f4 >> 3, c4 = (f4 & 7) << 2;
            ra[i] = *(const float4*)&A[(size_t)(row0 + r) * K + k0 + c4];
        }
#pragma unroll
        for (int i = 0; i < 2; i++) {
            int f4 = tid + i * 256;             // [0,512)
            int kk = f4 >> 4, n4 = (f4 & 15) << 2;
            rb[i] = *(const float4*)&W[(size_t)(k0 + kk) * M + col0 + n4];
        }
    };
    auto sts_tile = [&](int st) {
#pragma unroll
        for (int i = 0; i < 4; i++) {
            int f4 = tid + i * 256;
            int r = f4 >> 3, c4 = (f4 & 7) << 2;
            int mb = r >> 4;
            const float* pv = &ra[i].x;
#pragma unroll
            for (int j = 0; j < 4; j++) {
                int cc = c4 + j;
                int kc = cc >> 3, c8 = cc & 7;
                int lt = ((r & 7) << 2) | (c8 & 3);
                int f  = ((r >> 3) & 1) | ((c8 >> 2) << 1);
                sA[st][(((kc << 3) + mb) << 7) + (lt << 2) + f] = f2tf32(pv[j]);
            }
        }
#pragma unroll
        for (int i = 0; i < 2; i++) {
            int f4 = tid + i * 256;
            int kk = f4 >> 4, n4 = (f4 & 15) << 2;
            int kc = kk >> 3, c8 = kk & 7;
            int f  = c8 >> 2;
            const float* pv = &rb[i].x;
#pragma unroll
            for (int j = 0; j < 4; j++) {
                int n = n4 + j;
                int nb = n >> 3, g = n & 7;
                int lt = (g << 2) | (c8 & 3);
                sB[st][(((kc << 3) + nb) << 6) + (lt << 1) + f] = f2tf32(pv[j]);
            }
        }
    };

    // prologue
    ldg_tile(0);
    sts_tile(0);
    __syncthreads();

    for (int kt = 0; kt < KT; kt++) {
        const int st = kt & 1;
        if (kt + 1 < KT) ldg_tile(kt + 1);

        // compute current stage
#pragma unroll
        for (int kc = 0; kc < 4; kc++) {
            uint32_t af[4][4];
#pragma unroll
            for (int mt = 0; mt < 4; mt++) {
                int mb = (warpM << 2) + mt;
                uint4 v = *(const uint4*)&sA[st][(((kc << 3) + mb) << 7) + (lane << 2)];
                af[mt][0] = v.x; af[mt][1] = v.y; af[mt][2] = v.z; af[mt][3] = v.w;
            }
            uint32_t bf_[2][2];
#pragma unroll
            for (int nt = 0; nt < 2; nt++) {
                int nb = (warpN << 1) + nt;
                uint2 v = *(const uint2*)&sB[st][(((kc << 3) + nb) << 6) + (lane << 1)];
                bf_[nt][0] = v.x; bf_[nt][1] = v.y;
            }
#pragma unroll
            for (int mt = 0; mt < 4; mt++)
#pragma unroll
                for (int nt = 0; nt < 2; nt++)
                    mma_tf32(acc[mt][nt], af[mt], bf_[nt]);
        }

        if (kt + 1 < KT) sts_tile(st ^ 1);
        __syncthreads();
    }

    // epilogue
    const int g = lane >> 2, t = lane & 3;
#pragma unroll
    for (int mt = 0; mt < 4; mt++) {
        int r_lo = row0 + (warpM << 6) + (mt << 4) + g;
        int r_hi = r_lo + 8;
#pragma unroll
        for (int nt = 0; nt < 2; nt++) {
            int col = col0 + (warpN << 4) + (nt << 3) + (t << 1);
            float2 v0 = make_float2(acc[mt][nt][0], acc[mt][nt][1]);
            float2 v1 = make_float2(acc[mt][nt][2], acc[mt][nt][3]);
            if (BIAS) {
                float2 bv = *(const float2*)&bias[col];
                v0.x += bv.x; v0.y += bv.y;
                v1.x += bv.x; v1.y += bv.y;
            }
            if (RESID) {
                float2 q0 = *(const float2*)&resid[(size_t)r_lo * M + col];
                float2 q1 = *(const float2*)&resid[(size_t)r_hi * M + col];
                v0.x += q0.x; v0.y += q0.y;
                v1.x += q1.x; v1.y += q1.y;
            }
            if (RELU) {
                v0.x = fmaxf(v0.x, 0.f); v0.y = fmaxf(v0.y, 0.f);
                v1.x = fmaxf(v1.x, 0.f); v1.y = fmaxf(v1.y, 0.f);
            }
            *(float2*)&C[(size_t)r_lo * M + col] = v0;
            *(float2*)&C[(size_t)r_hi * M + col] = v1;
        }
    }
}

// ---------------- LayerNorm: one warp per token ------------------------------
__global__ void ln_kernel(const float* __restrict__ x,
                          const float* __restrict__ g,
                          const float* __restrict__ be,
                          float* __restrict__ out)
{
    int warp = (blockIdx.x * blockDim.x + threadIdx.x) >> 5;
    int lane = threadIdx.x & 31;
    if (warp >= NTOK) return;
    const float* row = x + (size_t)warp * DIM;
    float v[12];
    float s = 0.f, ss = 0.f;
#pragma unroll
    for (int i = 0; i < 12; i++) {
        v[i] = row[lane + 32 * i];
        s  += v[i];
        ss += v[i] * v[i];
    }
#pragma unroll
    for (int o = 16; o; o >>= 1) {
        s  += __shfl_xor_sync(0xffffffffu, s, o);
        ss += __shfl_xor_sync(0xffffffffu, ss, o);
    }
    float mean = s * (1.0f / DIM);
    float var  = ss * (1.0f / DIM) - mean * mean;
    float rstd = rsqrtf(var + 1e-5f);
    float* orow = out + (size_t)warp * DIM;
#pragma unroll
    for (int i = 0; i < 12; i++) {
        int c = lane + 32 * i;
        orow[c] = (v[i] - mean) * rstd * g[c] + be[c];
    }
}

// ---------------- Causal flash attention (fp32) ------------------------------
__global__ void __launch_bounds__(256)
attn_kernel(const float* __restrict__ q, const float* __restrict__ k,
            const float* __restrict__ v, float* __restrict__ ctx)
{
    extern __shared__ float sm[];
    float* Qst   = sm;
    float* Kst   = Qst + 64 * 64;
    float* Vs    = Kst + 64 * 64;
    float* Ss    = Vs + 64 * 64;
    float* alphas = Ss + 64 * 65;
    float* m_s   = alphas + 64;
    float* l_s   = m_s + 64;

    int qt = blockIdx.x;
    int h  = blockIdx.y;
    int b  = blockIdx.z;
    int tid = threadIdx.x;
    int tx = tid & 15, ty = tid >> 4;

    const float* qbase = q + (size_t)b * SEQ * DIM + h * HDIM;
    const float* kbase = k + (size_t)b * SEQ * DIM + h * HDIM;
    const float* vbase = v + (size_t)b * SEQ * DIM + h * HDIM;

#pragma unroll
    for (int i = 0; i < 4; i++) {
        int f = tid + i * 256;
        int r = f >> 4, d4 = (f & 15) << 2;
        float4 val = *(const float4*)&qbase[(size_t)(qt * 64 + r) * DIM + d4];
        Qst[(d4 + 0) * 64 + r] = val.x;
        Qst[(d4 + 1) * 64 + r] = val.y;
        Qst[(d4 + 2) * 64 + r] = val.z;
        Qst[(d4 + 3) * 64 + r] = val.w;
    }
    if (tid < 64) { m_s[tid] = -1e30f; l_s[tid] = 0.f; }

    float o[4][4] = {{0.f}};

    for (int kt = 0; kt <= qt; kt++) {
        __syncthreads();
#pragma unroll
        for (int i = 0; i < 4; i++) {
            int f = tid + i * 256;
            int r = f >> 4, d4 = (f & 15) << 2;
            float4 val = *(const float4*)&kbase[(size_t)(kt * 64 + r) * DIM + d4];
            Kst[(d4 + 0) * 64 + r] = val.x;
            Kst[(d4 + 1) * 64 + r] = val.y;
            Kst[(d4 + 2) * 64 + r] = val.z;
            Kst[(d4 + 3) * 64 + r] = val.w;
        }
        __syncthreads();

        float s_[4][4] = {{0.f}};
#pragma unroll
        for (int d = 0; d < 64; d++) {
            float4 a  = *(float4*)&Qst[d * 64 + ty * 4];
            float4 bq = *(float4*)&Kst[d * 64 + tx * 4];
            s_[0][0] += a.x * bq.x; s_[0][1] += a.x * bq.y; s_[0][2] += a.x * bq.z; s_[0][3] += a.x * bq.w;
            s_[1][0] += a.y * bq.x; s_[1][1] += a.y * bq.y; s_[1][2] += a.y * bq.z; s_[1][3] += a.y * bq.w;
            s_[2][0] += a.z * bq.x; s_[2][1] += a.z * bq.y; s_[2][2] += a.z * bq.z; s_[2][3] += a.z * bq.w;
            s_[3][0] += a.w * bq.x; s_[3][1] += a.w * bq.y; s_[3][2] += a.w * bq.z; s_[3][3] += a.w * bq.w;
        }
#pragma unroll
        for (int i = 0; i < 4; i++) {
#pragma unroll
            for (int j = 0; j < 4; j++) {
                int qi = ty * 4 + i, kj = tx * 4 + j;
                float val = s_[i][j] * 0.125f;
                if (kt * 64 + kj > qt * 64 + qi) val = -1e30f;
                Ss[qi * 65 + kj] = val;
            }
        }
        __syncthreads();

#pragma unroll
        for (int i = 0; i < 4; i++) {
            int f = tid + i * 256;
            int r = f >> 4, d4 = (f & 15) << 2;
            float4 val = *(const float4*)&vbase[(size_t)(kt * 64 + r) * DIM + d4];
            *(float4*)&Vs[r * 64 + d4] = val;
        }
        if (tid < 64) {
            float m_old = m_s[tid];
            float mt = m_old;
#pragma unroll 8
            for (int c = 0; c < 64; c++) mt = fmaxf(mt, Ss[tid * 65 + c]);
            float alpha = __expf(m_old - mt);
            float sum = 0.f;
#pragma unroll 8
            for (int c = 0; c < 64; c++) {
                float p = __expf(Ss[tid * 65 + c] - mt);
                Ss[tid * 65 + c] = p;
                sum += p;
            }
            m_s[tid] = mt;
            l_s[tid] = l_s[tid] * alpha + sum;
            alphas[tid] = alpha;
        }
        __syncthreads();

#pragma unroll
        for (int i = 0; i < 4; i++) {
            float al = alphas[ty * 4 + i];
            o[i][0] *= al; o[i][1] *= al; o[i][2] *= al; o[i][3] *= al;
        }
#pragma unroll
        for (int kk = 0; kk < 64; kk++) {
            float4 bv = *(float4*)&Vs[kk * 64 + tx * 4];
            float a0 = Ss[(ty * 4 + 0) * 65 + kk];
            float a1 = Ss[(ty * 4 + 1) * 65 + kk];
            float a2 = Ss[(ty * 4 + 2) * 65 + kk];
            float a3 = Ss[(ty * 4 + 3) * 65 + kk];
            o[0][0] += a0 * bv.x; o[0][1] += a0 * bv.y; o[0][2] += a0 * bv.z; o[0][3] += a0 * bv.w;
            o[1][0] += a1 * bv.x; o[1][1] += a1 * bv.y; o[1][2] += a1 * bv.z; o[1][3] += a1 * bv.w;
            o[2][0] += a2 * bv.x; o[2][1] += a2 * bv.y; o[2][2] += a2 * bv.z; o[2][3] += a2 * bv.w;
            o[3][0] += a3 * bv.x; o[3][1] += a3 * bv.y; o[3][2] += a3 * bv.z; o[3][3] += a3 * bv.w;
        }
    }

    float* obase = ctx + (size_t)b * SEQ * DIM + h * HDIM;
#pragma unroll
    for (int i = 0; i < 4; i++) {
        int qi = ty * 4 + i;
        float inv_l = 1.0f / l_s[qi];
        float4 val;
        val.x = o[i][0] * inv_l;
        val.y = o[i][1] * inv_l;
        val.z = o[i][2] * inv_l;
        val.w = o[i][3] * inv_l;
        *(float4*)&obase[(size_t)(qt * 64 + qi) * DIM + tx * 4] = val;
    }
}

// ---------------- launch ------------------------------------------------------
static float* dev_ptr(const void* sym)
{
    void* p = nullptr;
    cudaGetSymbolAddress(&p, sym);
    return (float*)p;
}

extern "C" void kernel_launch(void* const* d_in, const int* in_sizes, int n_in,
                              void* d_out, int out_size)
{
    (void)in_sizes; (void)n_in; (void)out_size;
    const float* x   = (const float*)d_in[0];
    const float* wq  = (const float*)d_in[1];
    const float* wk  = (const float*)d_in[2];
    const float* wv  = (const float*)d_in[3];
    const float* wo  = (const float*)d_in[4];
    const float* bo  = (const float*)d_in[5];
    const float* w1  = (const float*)d_in[6];
    const float* b1  = (const float*)d_in[7];
    const float* w2  = (const float*)d_in[8];
    const float* b2  = (const float*)d_in[9];
    const float* g1  = (const float*)d_in[10];
    const float* be1 = (const float*)d_in[11];
    const float* g2  = (const float*)d_in[12];
    const float* be2 = (const float*)d_in[13];
    float* out = (float*)d_out;

    float* h   = dev_ptr(g_h);
    float* qb  = dev_ptr(g_q);
    float* kb  = dev_ptr(g_k);
    float* vb  = dev_ptr(g_v);
    float* ctx = dev_ptr(g_ctx);
    float* x1  = dev_ptr(g_x1);
    float* ff  = dev_ptr(g_ff);

    const int ATTN_SMEM = (64 * 64 * 3 + 64 * 65 + 64 * 3) * sizeof(float); // 66560
    cudaFuncSetAttribute(attn_kernel, cudaFuncAttributeMaxDynamicSharedMemorySize, ATTN_SMEM);

    dim3 gridD(NTOK / 128, DIM / 64);      // 128 x 6
    dim3 gridF(NTOK / 128, FFDIM / 64);    // 128 x 24

    // LN1
    ln_kernel<<<NTOK / 8, 256>>>(x, g1, be1, h);
    // QKV projections (tf32 mma.sync)
    mma_gemm_kernel<false, false, false><<<gridD, 256>>>(h, wq, nullptr, nullptr, qb, DIM, DIM);
    mma_gemm_kernel<false, false, false><<<gridD, 256>>>(h, wk, nullptr, nullptr, kb, DIM, DIM);
    mma_gemm_kernel<false, false, false><<<gridD, 256>>>(h, wv, nullptr, nullptr, vb, DIM, DIM);
    // attention (fp32)
    attn_kernel<<<dim3(SEQ / 64, NHEAD, BATCH), 256, ATTN_SMEM>>>(qb, kb, vb, ctx);
    // output projection + residual
    mma_gemm_kernel<false, true, true><<<gridD, 256>>>(ctx, wo, bo, x, x1, DIM, DIM);
    // LN2
    ln_kernel<<<NTOK / 8, 256>>>(x1, g2, be2, h);
    // FFN
    mma_gemm_kernel<true, true, false><<<gridF, 256>>>(h, w1, b1, nullptr, ff, DIM, FFDIM);
    mma_gemm_kernel<false, true, true><<<gridD, 256>>>(ff, w2, b2, x1, out, FFDIM, DIM);
}

// round 5
// speedup vs baseline: 3.0259x; 2.4340x over previous
#include <cuda_runtime.h>
#include <cuda_bf16.h>
#include <cstdint>
#include <math.h>

// Problem dims
#define BATCH 64
#define SEQ   256
#define DIM   384
#define NHEAD 6
#define HDIM  64
#define NTOK  (BATCH * SEQ)      // 16384
#define FFDIM (4 * DIM)          // 1536

// ---------------- scratch (static device globals; no allocation) -------------
__device__ float g_h  [NTOK * DIM];
__device__ float g_q  [NTOK * DIM];
__device__ float g_k  [NTOK * DIM];
__device__ float g_v  [NTOK * DIM];
__device__ float g_ctx[NTOK * DIM];
__device__ float g_x1 [NTOK * DIM];
__device__ float g_ff [NTOK * FFDIM];

// ---------------- PTX helpers -------------------------------------------------
__device__ __forceinline__ uint32_t smem_u32(const void* p) {
    uint32_t a;
    asm("{ .reg .u64 t; cvta.to.shared.u64 t, %1; cvt.u32.u64 %0, t; }"
        : "=r"(a) : "l"(p));
    return a;
}
__device__ __forceinline__ void cp_async16(uint32_t dst, const void* src) {
    asm volatile("cp.async.cg.shared.global [%0], [%1], 16;" :: "r"(dst), "l"(src));
}
__device__ __forceinline__ void cp_commit() {
    asm volatile("cp.async.commit_group;" ::: "memory");
}
template<int N> __device__ __forceinline__ void cp_wait() {
    asm volatile("cp.async.wait_group %0;" :: "n"(N) : "memory");
}
__device__ __forceinline__ void mma_tf32(float* c, const uint32_t* a, const uint32_t* b) {
    asm volatile(
        "mma.sync.aligned.m16n8k8.row.col.f32.tf32.tf32.f32 "
        "{%0,%1,%2,%3}, {%4,%5,%6,%7}, {%8,%9}, {%0,%1,%2,%3};"
        : "+f"(c[0]), "+f"(c[1]), "+f"(c[2]), "+f"(c[3])
        : "r"(a[0]), "r"(a[1]), "r"(a[2]), "r"(a[3]), "r"(b[0]), "r"(b[1]));
}
__device__ __forceinline__ uint32_t lds32(uint32_t addr) {
    uint32_t v;
    asm volatile("ld.shared.b32 %0, [%1];" : "=r"(v) : "r"(addr));
    return v;
}

// ================= tf32 mma.sync GEMM, cp.async 3-stage pipeline ==============
// A: [N,K] row-major fp32, W: [K,M] row-major fp32, C: [N,M] = act(A@W+bias+resid)
// CTA tile 128x128, BK=32. 8 warps (warpM 0..1 x warpN 0..3), warp tile 64x32.
// smem per stage: A row-major stride 36 floats (36 % 32 == 4 -> banks 4g+t, all
// distinct); B row-major (k rows) stride 136 floats (136 % 32 == 8 -> banks
// 8t+g, all distinct). Raw fp32 stored; tf32 MMA truncates mantissa in HW.
#define STAGES   3
#define BK       32
#define A_STRIDE 36
#define B_STRIDE 136
#define SA_BYTES (128 * A_STRIDE * 4)          // 18432
#define SB_BYTES (BK * B_STRIDE * 4)           // 17408
#define STAGE_BYTES (SA_BYTES + SB_BYTES)      // 35840
#define GEMM_SMEM (STAGES * STAGE_BYTES)       // 107520

template<bool RELU, bool BIAS, bool RESID>
__global__ void __launch_bounds__(256, 2)
tf32_gemm_kernel(const float* __restrict__ A, const float* __restrict__ W,
                 const float* __restrict__ bias, const float* __restrict__ resid,
                 float* __restrict__ C, int K, int M)
{
    extern __shared__ char smem[];
    const uint32_t sb = smem_u32(smem);

    const int tid  = threadIdx.x;
    const int wid  = tid >> 5;
    const int lane = tid & 31;
    const int warpM = wid & 1;          // 0..1 -> 64 rows
    const int warpN = wid >> 1;         // 0..3 -> 32 cols
    const int g = lane >> 2, t = lane & 3;
    const int row0 = blockIdx.x * 128;
    const int col0 = blockIdx.y * 128;

    float acc[4][4][4];
#pragma unroll
    for (int mt = 0; mt < 4; mt++)
#pragma unroll
        for (int nt = 0; nt < 4; nt++)
#pragma unroll
            for (int f = 0; f < 4; f++) acc[mt][nt][f] = 0.f;

    const int KT = K >> 5;

    // copy stage kt into buffer st (8 cp.async / thread)
    auto copy_stage = [&](int kt, int st) {
        const int k0 = kt << 5;
        const uint32_t abase = sb + st * STAGE_BYTES;
        const uint32_t bbase = abase + SA_BYTES;
#pragma unroll
        for (int i = 0; i < 4; i++) {
            int c = tid + (i << 8);                // [0,1024)
            int r = c >> 3, c4 = (c & 7) << 2;
            cp_async16(abase + r * (A_STRIDE * 4) + (c4 << 2),
                       &A[(size_t)(row0 + r) * K + k0 + c4]);
        }
#pragma unroll
        for (int i = 0; i < 4; i++) {
            int c = tid + (i << 8);                // [0,1024)
            int r = c >> 5, n4 = (c & 31) << 2;
            cp_async16(bbase + r * (B_STRIDE * 4) + (n4 << 2),
                       &W[(size_t)(k0 + r) * M + col0 + n4]);
        }
    };

    // prologue: prefetch STAGES-1 stages
    copy_stage(0, 0); cp_commit();
    copy_stage(1, 1); cp_commit();

    for (int kt = 0; kt < KT; kt++) {
        const int st = kt % STAGES;
        // prefetch stage kt+2 (buffer computed at kt-1; safe after trailing sync)
        if (kt + STAGES - 1 < KT) copy_stage(kt + STAGES - 1, (kt + STAGES - 1) % STAGES);
        cp_commit();                     // empty group at tail keeps counts aligned
        cp_wait<STAGES - 1>();           // stage kt resident
        __syncthreads();

        const uint32_t aB = sb + st * STAGE_BYTES
                          + (warpM * 64 + g) * (A_STRIDE * 4) + (t << 2);
        const uint32_t bB = sb + st * STAGE_BYTES + SA_BYTES
                          + t * (B_STRIDE * 4) + ((warpN * 32 + g) << 2);
#pragma unroll
        for (int kc = 0; kc < 4; kc++) {
            uint32_t a_[4][4], b_[4][2];
#pragma unroll
            for (int mt = 0; mt < 4; mt++) {
                uint32_t base = aB + mt * 16 * (A_STRIDE * 4) + (kc << 5);
                a_[mt][0] = lds32(base);
                a_[mt][1] = lds32(base + 8 * (A_STRIDE * 4));
                a_[mt][2] = lds32(base + 16);
                a_[mt][3] = lds32(base + 8 * (A_STRIDE * 4) + 16);
            }
#pragma unroll
            for (int nt = 0; nt < 4; nt++) {
                uint32_t base = bB + kc * 8 * (B_STRIDE * 4) + (nt << 5);
                b_[nt][0] = lds32(base);
                b_[nt][1] = lds32(base + 4 * (B_STRIDE * 4));
            }
#pragma unroll
            for (int mt = 0; mt < 4; mt++)
#pragma unroll
                for (int nt = 0; nt < 4; nt++)
                    mma_tf32(acc[mt][nt], a_[mt], b_[nt]);
        }
        __syncthreads();
    }

    // epilogue
#pragma unroll
    for (int mt = 0; mt < 4; mt++) {
        int r_lo = row0 + warpM * 64 + mt * 16 + g;
        int r_hi = r_lo + 8;
#pragma unroll
        for (int nt = 0; nt < 4; nt++) {
            int col = col0 + warpN * 32 + nt * 8 + (t << 1);
            float2 v0 = make_float2(acc[mt][nt][0], acc[mt][nt][1]);
            float2 v1 = make_float2(acc[mt][nt][2], acc[mt][nt][3]);
            if (BIAS) {
                float2 bv = *(const float2*)&bias[col];
                v0.x += bv.x; v0.y += bv.y;
                v1.x += bv.x; v1.y += bv.y;
            }
            if (RESID) {
                float2 q0 = *(const float2*)&resid[(size_t)r_lo * M + col];
                float2 q1 = *(const float2*)&resid[(size_t)r_hi * M + col];
                v0.x += q0.x; v0.y += q0.y;
                v1.x += q1.x; v1.y += q1.y;
            }
            if (RELU) {
                v0.x = fmaxf(v0.x, 0.f); v0.y = fmaxf(v0.y, 0.f);
                v1.x = fmaxf(v1.x, 0.f); v1.y = fmaxf(v1.y, 0.f);
            }
            *(float2*)&C[(size_t)r_lo * M + col] = v0;
            *(float2*)&C[(size_t)r_hi * M + col] = v1;
        }
    }
}

// ---------------- LayerNorm: one warp per token ------------------------------
__global__ void ln_kernel(const float* __restrict__ x,
                          const float* __restrict__ g,
                          const float* __restrict__ be,
                          float* __restrict__ out)
{
    int warp = (blockIdx.x * blockDim.x + threadIdx.x) >> 5;
    int lane = threadIdx.x & 31;
    if (warp >= NTOK) return;
    const float* row = x + (size_t)warp * DIM;
    float v[12];
    float s = 0.f, ss = 0.f;
#pragma unroll
    for (int i = 0; i < 12; i++) {
        v[i] = row[lane + 32 * i];
        s  += v[i];
        ss += v[i] * v[i];
    }
#pragma unroll
    for (int o = 16; o; o >>= 1) {
        s  += __shfl_xor_sync(0xffffffffu, s, o);
        ss += __shfl_xor_sync(0xffffffffu, ss, o);
    }
    float mean = s * (1.0f / DIM);
    float var  = ss * (1.0f / DIM) - mean * mean;
    float rstd = rsqrtf(var + 1e-5f);
    float* orow = out + (size_t)warp * DIM;
#pragma unroll
    for (int i = 0; i < 12; i++) {
        int c = lane + 32 * i;
        orow[c] = (v[i] - mean) * rstd * g[c] + be[c];
    }
}

// ---------------- Causal flash attention (fp32) ------------------------------
__global__ void __launch_bounds__(256)
attn_kernel(const float* __restrict__ q, const float* __restrict__ k,
            const float* __restrict__ v, float* __restrict__ ctx)
{
    extern __shared__ float sm[];
    float* Qst   = sm;
    float* Kst   = Qst + 64 * 64;
    float* Vs    = Kst + 64 * 64;
    float* Ss    = Vs + 64 * 64;
    float* alphas = Ss + 64 * 65;
    float* m_s   = alphas + 64;
    float* l_s   = m_s + 64;

    int qt = blockIdx.x;
    int h  = blockIdx.y;
    int b  = blockIdx.z;
    int tid = threadIdx.x;
    int tx = tid & 15, ty = tid >> 4;

    const float* qbase = q + (size_t)b * SEQ * DIM + h * HDIM;
    const float* kbase = k + (size_t)b * SEQ * DIM + h * HDIM;
    const float* vbase = v + (size_t)b * SEQ * DIM + h * HDIM;

#pragma unroll
    for (int i = 0; i < 4; i++) {
        int f = tid + i * 256;
        int r = f >> 4, d4 = (f & 15) << 2;
        float4 val = *(const float4*)&qbase[(size_t)(qt * 64 + r) * DIM + d4];
        Qst[(d4 + 0) * 64 + r] = val.x;
        Qst[(d4 + 1) * 64 + r] = val.y;
        Qst[(d4 + 2) * 64 + r] = val.z;
        Qst[(d4 + 3) * 64 + r] = val.w;
    }
    if (tid < 64) { m_s[tid] = -1e30f; l_s[tid] = 0.f; }

    float o[4][4] = {{0.f}};

    for (int kt = 0; kt <= qt; kt++) {
        __syncthreads();
#pragma unroll
        for (int i = 0; i < 4; i++) {
            int f = tid + i * 256;
            int r = f >> 4, d4 = (f & 15) << 2;
            float4 val = *(const float4*)&kbase[(size_t)(kt * 64 + r) * DIM + d4];
            Kst[(d4 + 0) * 64 + r] = val.x;
            Kst[(d4 + 1) * 64 + r] = val.y;
            Kst[(d4 + 2) * 64 + r] = val.z;
            Kst[(d4 + 3) * 64 + r] = val.w;
        }
        __syncthreads();

        float s_[4][4] = {{0.f}};
#pragma unroll
        for (int d = 0; d < 64; d++) {
            float4 a  = *(float4*)&Qst[d * 64 + ty * 4];
            float4 bq = *(float4*)&Kst[d * 64 + tx * 4];
            s_[0][0] += a.x * bq.x; s_[0][1] += a.x * bq.y; s_[0][2] += a.x * bq.z; s_[0][3] += a.x * bq.w;
            s_[1][0] += a.y * bq.x; s_[1][1] += a.y * bq.y; s_[1][2] += a.y * bq.z; s_[1][3] += a.y * bq.w;
            s_[2][0] += a.z * bq.x; s_[2][1] += a.z * bq.y; s_[2][2] += a.z * bq.z; s_[2][3] += a.z * bq.w;
            s_[3][0] += a.w * bq.x; s_[3][1] += a.w * bq.y; s_[3][2] += a.w * bq.z; s_[3][3] += a.w * bq.w;
        }
#pragma unroll
        for (int i = 0; i < 4; i++) {
#pragma unroll
            for (int j = 0; j < 4; j++) {
                int qi = ty * 4 + i, kj = tx * 4 + j;
                float val = s_[i][j] * 0.125f;
                if (kt * 64 + kj > qt * 64 + qi) val = -1e30f;
                Ss[qi * 65 + kj] = val;
            }
        }
        __syncthreads();

#pragma unroll
        for (int i = 0; i < 4; i++) {
            int f = tid + i * 256;
            int r = f >> 4, d4 = (f & 15) << 2;
            float4 val = *(const float4*)&vbase[(size_t)(kt * 64 + r) * DIM + d4];
            *(float4*)&Vs[r * 64 + d4] = val;
        }
        if (tid < 64) {
            float m_old = m_s[tid];
            float mt = m_old;
#pragma unroll 8
            for (int c = 0; c < 64; c++) mt = fmaxf(mt, Ss[tid * 65 + c]);
            float alpha = __expf(m_old - mt);
            float sum = 0.f;
#pragma unroll 8
            for (int c = 0; c < 64; c++) {
                float p = __expf(Ss[tid * 65 + c] - mt);
                Ss[tid * 65 + c] = p;
                sum += p;
            }
            m_s[tid] = mt;
            l_s[tid] = l_s[tid] * alpha + sum;
            alphas[tid] = alpha;
        }
        __syncthreads();

#pragma unroll
        for (int i = 0; i < 4; i++) {
            float al = alphas[ty * 4 + i];
            o[i][0] *= al; o[i][1] *= al; o[i][2] *= al; o[i][3] *= al;
        }
#pragma unroll
        for (int kk = 0; kk < 64; kk++) {
            float4 bv = *(float4*)&Vs[kk * 64 + tx * 4];
            float a0 = Ss[(ty * 4 + 0) * 65 + kk];
            float a1 = Ss[(ty * 4 + 1) * 65 + kk];
            float a2 = Ss[(ty * 4 + 2) * 65 + kk];
            float a3 = Ss[(ty * 4 + 3) * 65 + kk];
            o[0][0] += a0 * bv.x; o[0][1] += a0 * bv.y; o[0][2] += a0 * bv.z; o[0][3] += a0 * bv.w;
            o[1][0] += a1 * bv.x; o[1][1] += a1 * bv.y; o[1][2] += a1 * bv.z; o[1][3] += a1 * bv.w;
            o[2][0] += a2 * bv.x; o[2][1] += a2 * bv.y; o[2][2] += a2 * bv.z; o[2][3] += a2 * bv.w;
            o[3][0] += a3 * bv.x; o[3][1] += a3 * bv.y; o[3][2] += a3 * bv.z; o[3][3] += a3 * bv.w;
        }
    }

    float* obase = ctx + (size_t)b * SEQ * DIM + h * HDIM;
#pragma unroll
    for (int i = 0; i < 4; i++) {
        int qi = ty * 4 + i;
        float inv_l = 1.0f / l_s[qi];
        float4 val;
        val.x = o[i][0] * inv_l;
        val.y = o[i][1] * inv_l;
        val.z = o[i][2] * inv_l;
        val.w = o[i][3] * inv_l;
        *(float4*)&obase[(size_t)(qt * 64 + qi) * DIM + tx * 4] = val;
    }
}

// ---------------- launch ------------------------------------------------------
static float* dev_ptr(const void* sym)
{
    void* p = nullptr;
    cudaGetSymbolAddress(&p, sym);
    return (float*)p;
}

extern "C" void kernel_launch(void* const* d_in, const int* in_sizes, int n_in,
                              void* d_out, int out_size)
{
    (void)in_sizes; (void)n_in; (void)out_size;
    const float* x   = (const float*)d_in[0];
    const float* wq  = (const float*)d_in[1];
    const float* wk  = (const float*)d_in[2];
    const float* wv  = (const float*)d_in[3];
    const float* wo  = (const float*)d_in[4];
    const float* bo  = (const float*)d_in[5];
    const float* w1  = (const float*)d_in[6];
    const float* b1  = (const float*)d_in[7];
    const float* w2  = (const float*)d_in[8];
    const float* b2  = (const float*)d_in[9];
    const float* g1  = (const float*)d_in[10];
    const float* be1 = (const float*)d_in[11];
    const float* g2  = (const float*)d_in[12];
    const float* be2 = (const float*)d_in[13];
    float* out = (float*)d_out;

    float* h   = dev_ptr(g_h);
    float* qb  = dev_ptr(g_q);
    float* kb  = dev_ptr(g_k);
    float* vb  = dev_ptr(g_v);
    float* ctx = dev_ptr(g_ctx);
    float* x1  = dev_ptr(g_x1);
    float* ff  = dev_ptr(g_ff);

    const int ATTN_SMEM = (64 * 64 * 3 + 64 * 65 + 64 * 3) * sizeof(float); // 66560
    cudaFuncSetAttribute(attn_kernel, cudaFuncAttributeMaxDynamicSharedMemorySize, ATTN_SMEM);
    cudaFuncSetAttribute(tf32_gemm_kernel<false, false, false>,
                         cudaFuncAttributeMaxDynamicSharedMemorySize, GEMM_SMEM);
    cudaFuncSetAttribute(tf32_gemm_kernel<false, true, true>,
                         cudaFuncAttributeMaxDynamicSharedMemorySize, GEMM_SMEM);
    cudaFuncSetAttribute(tf32_gemm_kernel<true, true, false>,
                         cudaFuncAttributeMaxDynamicSharedMemorySize, GEMM_SMEM);

    dim3 gridD(NTOK / 128, DIM / 128);     // 128 x 3
    dim3 gridF(NTOK / 128, FFDIM / 128);   // 128 x 12

    // LN1
    ln_kernel<<<NTOK / 8, 256>>>(x, g1, be1, h);
    // QKV projections (tf32 mma.sync, cp.async pipeline)
    tf32_gemm_kernel<false, false, false><<<gridD, 256, GEMM_SMEM>>>(h, wq, nullptr, nullptr, qb, DIM, DIM);
    tf32_gemm_kernel<false, false, false><<<gridD, 256, GEMM_SMEM>>>(h, wk, nullptr, nullptr, kb, DIM, DIM);
    tf32_gemm_kernel<false, false, false><<<gridD, 256, GEMM_SMEM>>>(h, wv, nullptr, nullptr, vb, DIM, DIM);
    // attention (fp32)
    attn_kernel<<<dim3(SEQ / 64, NHEAD, BATCH), 256, ATTN_SMEM>>>(qb, kb, vb, ctx);
    // output projection + residual
    tf32_gemm_kernel<false, true, true><<<gridD, 256, GEMM_SMEM>>>(ctx, wo, bo, x, x1, DIM, DIM);
    // LN2
    ln_kernel<<<NTOK / 8, 256>>>(x1, g2, be2, h);
    // FFN
    tf32_gemm_kernel<true, true, false><<<gridF, 256, GEMM_SMEM>>>(h, w1, b1, nullptr, ff, DIM, FFDIM);
    tf32_gemm_kernel<false, true, true><<<gridD, 256, GEMM_SMEM>>>(ff, w2, b2, x1, out, FFDIM, DIM);
}

// round 6
// speedup vs baseline: 3.1875x; 1.0534x over previous
#include <cuda_runtime.h>
#include <cuda_bf16.h>
#include <cstdint>
#include <math.h>

// Problem dims
#define BATCH 64
#define SEQ   256
#define DIM   384
#define NHEAD 6
#define HDIM  64
#define NTOK  (BATCH * SEQ)      // 16384
#define FFDIM (4 * DIM)          // 1536

// ---------------- scratch (static device globals; no allocation) -------------
__device__ float g_h  [NTOK * DIM];
__device__ float g_q  [NTOK * DIM];
__device__ float g_k  [NTOK * DIM];
__device__ float g_v  [NTOK * DIM];
__device__ float g_ctx[NTOK * DIM];
__device__ float g_x1 [NTOK * DIM];
__device__ float g_ff [NTOK * FFDIM];

// ---------------- PTX helpers -------------------------------------------------
__device__ __forceinline__ uint32_t smem_u32(const void* p) {
    uint32_t a;
    asm("{ .reg .u64 t; cvta.to.shared.u64 t, %1; cvt.u32.u64 %0, t; }"
        : "=r"(a) : "l"(p));
    return a;
}
__device__ __forceinline__ void cp_async16(uint32_t dst, const void* src) {
    asm volatile("cp.async.cg.shared.global [%0], [%1], 16;" :: "r"(dst), "l"(src));
}
__device__ __forceinline__ void cp_commit() {
    asm volatile("cp.async.commit_group;" ::: "memory");
}
template<int N> __device__ __forceinline__ void cp_wait() {
    asm volatile("cp.async.wait_group %0;" :: "n"(N) : "memory");
}
__device__ __forceinline__ void mma_tf32(float* c, const uint32_t* a, const uint32_t* b) {
    asm volatile(
        "mma.sync.aligned.m16n8k8.row.col.f32.tf32.tf32.f32 "
        "{%0,%1,%2,%3}, {%4,%5,%6,%7}, {%8,%9}, {%0,%1,%2,%3};"
        : "+f"(c[0]), "+f"(c[1]), "+f"(c[2]), "+f"(c[3])
        : "r"(a[0]), "r"(a[1]), "r"(a[2]), "r"(a[3]), "r"(b[0]), "r"(b[1]));
}
__device__ __forceinline__ uint32_t lds32(uint32_t addr) {
    uint32_t v;
    asm volatile("ld.shared.b32 %0, [%1];" : "=r"(v) : "r"(addr));
    return v;
}

// ================= tf32 mma.sync GEMM, cp.async 2-stage, 128 threads ==========
// CTA tile 128x128, BK=32, 4 warps each computing a 64x64 quadrant
// (mt=4 x nt=8 m16n8k8 tiles). 2-stage pipeline -> 71.7KB smem -> 3 CTAs/SM.
// A smem stride 36 floats (banks 4g+t, conflict-free); B stride 136 (banks
// 8t+g+8nt, conflict-free). Raw fp32 stored; tf32 MMA truncates in HW.
#define BK       32
#define A_STRIDE 36
#define B_STRIDE 136
#define SA_BYTES (128 * A_STRIDE * 4)          // 18432
#define SB_BYTES (BK * B_STRIDE * 4)           // 17408
#define STAGE_BYTES (SA_BYTES + SB_BYTES)      // 35840
#define GEMM_SMEM (2 * STAGE_BYTES)            // 71680

template<bool RELU, bool BIAS, bool RESID>
__device__ __forceinline__ void gemm_body(
    uint32_t sb,
    const float* __restrict__ A, const float* __restrict__ W,
    const float* __restrict__ bias, const float* __restrict__ resid,
    float* __restrict__ C, int K, int M, int row0, int col0)
{
    const int tid  = threadIdx.x;
    const int wid  = tid >> 5;
    const int lane = tid & 31;
    const int warpM = wid & 1;          // 64 rows
    const int warpN = wid >> 1;         // 64 cols
    const int g = lane >> 2, t = lane & 3;

    float acc[4][8][4];
#pragma unroll
    for (int mt = 0; mt < 4; mt++)
#pragma unroll
        for (int nt = 0; nt < 8; nt++)
#pragma unroll
            for (int f = 0; f < 4; f++) acc[mt][nt][f] = 0.f;

    const int KT = K >> 5;

    auto copy_stage = [&](int kt, int st) {
        const int k0 = kt << 5;
        const uint32_t abase = sb + st * STAGE_BYTES;
        const uint32_t bbase = abase + SA_BYTES;
#pragma unroll
        for (int i = 0; i < 8; i++) {
            int c = tid + (i << 7);                // [0,1024)
            int r = c >> 3, c4 = (c & 7) << 2;
            cp_async16(abase + r * (A_STRIDE * 4) + (c4 << 2),
                       &A[(size_t)(row0 + r) * K + k0 + c4]);
        }
#pragma unroll
        for (int i = 0; i < 8; i++) {
            int c = tid + (i << 7);                // [0,1024)
            int r = c >> 5, n4 = (c & 31) << 2;
            cp_async16(bbase + r * (B_STRIDE * 4) + (n4 << 2),
                       &W[(size_t)(k0 + r) * M + col0 + n4]);
        }
    };

    copy_stage(0, 0);
    cp_commit();

    for (int kt = 0; kt < KT; kt++) {
        const int st = kt & 1;
        if (kt + 1 < KT) copy_stage(kt + 1, st ^ 1);
        cp_commit();
        cp_wait<1>();
        __syncthreads();

        const uint32_t aB = sb + st * STAGE_BYTES
                          + (warpM * 64 + g) * (A_STRIDE * 4) + (t << 2);
        const uint32_t bB = sb + st * STAGE_BYTES + SA_BYTES
                          + t * (B_STRIDE * 4) + ((warpN * 64 + g) << 2);
#pragma unroll
        for (int kc = 0; kc < 4; kc++) {
            uint32_t a_[4][4];
#pragma unroll
            for (int mt = 0; mt < 4; mt++) {
                uint32_t base = aB + mt * 16 * (A_STRIDE * 4) + (kc << 5);
                a_[mt][0] = lds32(base);
                a_[mt][1] = lds32(base + 8 * (A_STRIDE * 4));
                a_[mt][2] = lds32(base + 16);
                a_[mt][3] = lds32(base + 8 * (A_STRIDE * 4) + 16);
            }
#pragma unroll
            for (int nt = 0; nt < 8; nt++) {
                uint32_t base = bB + kc * 8 * (B_STRIDE * 4) + (nt << 5);
                uint32_t b_[2];
                b_[0] = lds32(base);
                b_[1] = lds32(base + 4 * (B_STRIDE * 4));
#pragma unroll
                for (int mt = 0; mt < 4; mt++)
                    mma_tf32(acc[mt][nt], a_[mt], b_);
            }
        }
        __syncthreads();
    }

    // epilogue
#pragma unroll
    for (int mt = 0; mt < 4; mt++) {
        int r_lo = row0 + warpM * 64 + mt * 16 + g;
        int r_hi = r_lo + 8;
#pragma unroll
        for (int nt = 0; nt < 8; nt++) {
            int col = col0 + warpN * 64 + nt * 8 + (t << 1);
            float2 v0 = make_float2(acc[mt][nt][0], acc[mt][nt][1]);
            float2 v1 = make_float2(acc[mt][nt][2], acc[mt][nt][3]);
            if (BIAS) {
                float2 bv = *(const float2*)&bias[col];
                v0.x += bv.x; v0.y += bv.y;
                v1.x += bv.x; v1.y += bv.y;
            }
            if (RESID) {
                float2 q0 = *(const float2*)&resid[(size_t)r_lo * M + col];
                float2 q1 = *(const float2*)&resid[(size_t)r_hi * M + col];
                v0.x += q0.x; v0.y += q0.y;
                v1.x += q1.x; v1.y += q1.y;
            }
            if (RELU) {
                v0.x = fmaxf(v0.x, 0.f); v0.y = fmaxf(v0.y, 0.f);
                v1.x = fmaxf(v1.x, 0.f); v1.y = fmaxf(v1.y, 0.f);
            }
            *(float2*)&C[(size_t)r_lo * M + col] = v0;
            *(float2*)&C[(size_t)r_hi * M + col] = v1;
        }
    }
}

template<bool RELU, bool BIAS, bool RESID>
__global__ void __launch_bounds__(128, 3)
tf32_gemm_kernel(const float* __restrict__ A, const float* __restrict__ W,
                 const float* __restrict__ bias, const float* __restrict__ resid,
                 float* __restrict__ C, int K, int M)
{
    extern __shared__ char smem[];
    gemm_body<RELU, BIAS, RESID>(smem_u32(smem), A, W, bias, resid, C, K, M,
                                 blockIdx.x * 128, blockIdx.y * 128);
}

// Fused QKV: blockIdx.y in [0,9): sel = y/3 picks (wq->q | wk->k | wv->v),
// (y%3)*128 is the column tile. One launch, 1152 CTAs.
__global__ void __launch_bounds__(128, 3)
qkv_gemm_kernel(const float* __restrict__ A,
                const float* __restrict__ wq, const float* __restrict__ wk,
                const float* __restrict__ wv,
                float* __restrict__ q, float* __restrict__ k, float* __restrict__ v)
{
    extern __shared__ char smem[];
    int y = blockIdx.y;
    int sel = y / 3;
    int col0 = (y - sel * 3) * 128;
    const float* W = (sel == 0) ? wq : (sel == 1) ? wk : wv;
    float* C = (sel == 0) ? q : (sel == 1) ? k : v;
    gemm_body<false, false, false>(smem_u32(smem), A, W, nullptr, nullptr, C,
                                   DIM, DIM, blockIdx.x * 128, col0);
}

// ---------------- LayerNorm: one warp per token ------------------------------
__global__ void ln_kernel(const float* __restrict__ x,
                          const float* __restrict__ g,
                          const float* __restrict__ be,
                          float* __restrict__ out)
{
    int warp = (blockIdx.x * blockDim.x + threadIdx.x) >> 5;
    int lane = threadIdx.x & 31;
    if (warp >= NTOK) return;
    const float* row = x + (size_t)warp * DIM;
    float v[12];
    float s = 0.f, ss = 0.f;
#pragma unroll
    for (int i = 0; i < 12; i++) {
        v[i] = row[lane + 32 * i];
        s  += v[i];
        ss += v[i] * v[i];
    }
#pragma unroll
    for (int o = 16; o; o >>= 1) {
        s  += __shfl_xor_sync(0xffffffffu, s, o);
        ss += __shfl_xor_sync(0xffffffffu, ss, o);
    }
    float mean = s * (1.0f / DIM);
    float var  = ss * (1.0f / DIM) - mean * mean;
    float rstd = rsqrtf(var + 1e-5f);
    float* orow = out + (size_t)warp * DIM;
#pragma unroll
    for (int i = 0; i < 12; i++) {
        int c = lane + 32 * i;
        orow[c] = (v[i] - mean) * rstd * g[c] + be[c];
    }
}

// ---------------- Causal flash attention (fp32) ------------------------------
__global__ void __launch_bounds__(256)
attn_kernel(const float* __restrict__ q, const float* __restrict__ k,
            const float* __restrict__ v, float* __restrict__ ctx)
{
    extern __shared__ float sm[];
    float* Qst   = sm;
    float* Kst   = Qst + 64 * 64;
    float* Vs    = Kst + 64 * 64;
    float* Ss    = Vs + 64 * 64;
    float* alphas = Ss + 64 * 65;
    float* m_s   = alphas + 64;
    float* l_s   = m_s + 64;

    int qt = blockIdx.x;
    int h  = blockIdx.y;
    int b  = blockIdx.z;
    int tid = threadIdx.x;
    int tx = tid & 15, ty = tid >> 4;

    const float* qbase = q + (size_t)b * SEQ * DIM + h * HDIM;
    const float* kbase = k + (size_t)b * SEQ * DIM + h * HDIM;
    const float* vbase = v + (size_t)b * SEQ * DIM + h * HDIM;

#pragma unroll
    for (int i = 0; i < 4; i++) {
        int f = tid + i * 256;
        int r = f >> 4, d4 = (f & 15) << 2;
        float4 val = *(const float4*)&qbase[(size_t)(qt * 64 + r) * DIM + d4];
        Qst[(d4 + 0) * 64 + r] = val.x;
        Qst[(d4 + 1) * 64 + r] = val.y;
        Qst[(d4 + 2) * 64 + r] = val.z;
        Qst[(d4 + 3) * 64 + r] = val.w;
    }
    if (tid < 64) { m_s[tid] = -1e30f; l_s[tid] = 0.f; }

    float o[4][4] = {{0.f}};

    for (int kt = 0; kt <= qt; kt++) {
        __syncthreads();
#pragma unroll
        for (int i = 0; i < 4; i++) {
            int f = tid + i * 256;
            int r = f >> 4, d4 = (f & 15) << 2;
            float4 val = *(const float4*)&kbase[(size_t)(kt * 64 + r) * DIM + d4];
            Kst[(d4 + 0) * 64 + r] = val.x;
            Kst[(d4 + 1) * 64 + r] = val.y;
            Kst[(d4 + 2) * 64 + r] = val.z;
            Kst[(d4 + 3) * 64 + r] = val.w;
        }
        __syncthreads();

        float s_[4][4] = {{0.f}};
#pragma unroll
        for (int d = 0; d < 64; d++) {
            float4 a  = *(float4*)&Qst[d * 64 + ty * 4];
            float4 bq = *(float4*)&Kst[d * 64 + tx * 4];
            s_[0][0] += a.x * bq.x; s_[0][1] += a.x * bq.y; s_[0][2] += a.x * bq.z; s_[0][3] += a.x * bq.w;
            s_[1][0] += a.y * bq.x; s_[1][1] += a.y * bq.y; s_[1][2] += a.y * bq.z; s_[1][3] += a.y * bq.w;
            s_[2][0] += a.z * bq.x; s_[2][1] += a.z * bq.y; s_[2][2] += a.z * bq.z; s_[2][3] += a.z * bq.w;
            s_[3][0] += a.w * bq.x; s_[3][1] += a.w * bq.y; s_[3][2] += a.w * bq.z; s_[3][3] += a.w * bq.w;
        }
#pragma unroll
        for (int i = 0; i < 4; i++) {
#pragma unroll
            for (int j = 0; j < 4; j++) {
                int qi = ty * 4 + i, kj = tx * 4 + j;
                float val = s_[i][j] * 0.125f;
                if (kt * 64 + kj > qt * 64 + qi) val = -1e30f;
                Ss[qi * 65 + kj] = val;
            }
        }
        __syncthreads();

#pragma unroll
        for (int i = 0; i < 4; i++) {
            int f = tid + i * 256;
            int r = f >> 4, d4 = (f & 15) << 2;
            float4 val = *(const float4*)&vbase[(size_t)(kt * 64 + r) * DIM + d4];
            *(float4*)&Vs[r * 64 + d4] = val;
        }
        if (tid < 64) {
            float m_old = m_s[tid];
            float mt = m_old;
#pragma unroll 8
            for (int c = 0; c < 64; c++) mt = fmaxf(mt, Ss[tid * 65 + c]);
            float alpha = __expf(m_old - mt);
            float sum = 0.f;
#pragma unroll 8
            for (int c = 0; c < 64; c++) {
                float p = __expf(Ss[tid * 65 + c] - mt);
                Ss[tid * 65 + c] = p;
                sum += p;
            }
            m_s[tid] = mt;
            l_s[tid] = l_s[tid] * alpha + sum;
            alphas[tid] = alpha;
        }
        __syncthreads();

#pragma unroll
        for (int i = 0; i < 4; i++) {
            float al = alphas[ty * 4 + i];
            o[i][0] *= al; o[i][1] *= al; o[i][2] *= al; o[i][3] *= al;
        }
#pragma unroll
        for (int kk = 0; kk < 64; kk++) {
            float4 bv = *(float4*)&Vs[kk * 64 + tx * 4];
            float a0 = Ss[(ty * 4 + 0) * 65 + kk];
            float a1 = Ss[(ty * 4 + 1) * 65 + kk];
            float a2 = Ss[(ty * 4 + 2) * 65 + kk];
            float a3 = Ss[(ty * 4 + 3) * 65 + kk];
            o[0][0] += a0 * bv.x; o[0][1] += a0 * bv.y; o[0][2] += a0 * bv.z; o[0][3] += a0 * bv.w;
            o[1][0] += a1 * bv.x; o[1][1] += a1 * bv.y; o[1][2] += a1 * bv.z; o[1][3] += a1 * bv.w;
            o[2][0] += a2 * bv.x; o[2][1] += a2 * bv.y; o[2][2] += a2 * bv.z; o[2][3] += a2 * bv.w;
            o[3][0] += a3 * bv.x; o[3][1] += a3 * bv.y; o[3][2] += a3 * bv.z; o[3][3] += a3 * bv.w;
        }
    }

    float* obase = ctx + (size_t)b * SEQ * DIM + h * HDIM;
#pragma unroll
    for (int i = 0; i < 4; i++) {
        int qi = ty * 4 + i;
        float inv_l = 1.0f / l_s[qi];
        float4 val;
        val.x = o[i][0] * inv_l;
        val.y = o[i][1] * inv_l;
        val.z = o[i][2] * inv_l;
        val.w = o[i][3] * inv_l;
        *(float4*)&obase[(size_t)(qt * 64 + qi) * DIM + tx * 4] = val;
    }
}

// ---------------- launch ------------------------------------------------------
static float* dev_ptr(const void* sym)
{
    void* p = nullptr;
    cudaGetSymbolAddress(&p, sym);
    return (float*)p;
}

extern "C" void kernel_launch(void* const* d_in, const int* in_sizes, int n_in,
                              void* d_out, int out_size)
{
    (void)in_sizes; (void)n_in; (void)out_size;
    const float* x   = (const float*)d_in[0];
    const float* wq  = (const float*)d_in[1];
    const float* wk  = (const float*)d_in[2];
    const float* wv  = (const float*)d_in[3];
    const float* wo  = (const float*)d_in[4];
    const float* bo  = (const float*)d_in[5];
    const float* w1  = (const float*)d_in[6];
    const float* b1  = (const float*)d_in[7];
    const float* w2  = (const float*)d_in[8];
    const float* b2  = (const float*)d_in[9];
    const float* g1  = (const float*)d_in[10];
    const float* be1 = (const float*)d_in[11];
    const float* g2  = (const float*)d_in[12];
    const float* be2 = (const float*)d_in[13];
    float* out = (float*)d_out;

    float* h   = dev_ptr(g_h);
    float* qb  = dev_ptr(g_q);
    float* kb  = dev_ptr(g_k);
    float* vb  = dev_ptr(g_v);
    float* ctx = dev_ptr(g_ctx);
    float* x1  = dev_ptr(g_x1);
    float* ff  = dev_ptr(g_ff);

    const int ATTN_SMEM = (64 * 64 * 3 + 64 * 65 + 64 * 3) * sizeof(float); // 66560
    cudaFuncSetAttribute(attn_kernel, cudaFuncAttributeMaxDynamicSharedMemorySize, ATTN_SMEM);
    cudaFuncSetAttribute(qkv_gemm_kernel,
                         cudaFuncAttributeMaxDynamicSharedMemorySize, GEMM_SMEM);
    cudaFuncSetAttribute(tf32_gemm_kernel<false, true, true>,
                         cudaFuncAttributeMaxDynamicSharedMemorySize, GEMM_SMEM);
    cudaFuncSetAttribute(tf32_gemm_kernel<true, true, false>,
                         cudaFuncAttributeMaxDynamicSharedMemorySize, GEMM_SMEM);

    // LN1
    ln_kernel<<<NTOK / 8, 256>>>(x, g1, be1, h);
    // fused QKV projections
    qkv_gemm_kernel<<<dim3(NTOK / 128, 9), 128, GEMM_SMEM>>>(h, wq, wk, wv, qb, kb, vb);
    // attention (fp32)
    attn_kernel<<<dim3(SEQ / 64, NHEAD, BATCH), 256, ATTN_SMEM>>>(qb, kb, vb, ctx);
    // output projection + residual
    tf32_gemm_kernel<false, true, true><<<dim3(NTOK / 128, 3), 128, GEMM_SMEM>>>(ctx, wo, bo, x, x1, DIM, DIM);
    // LN2
    ln_kernel<<<NTOK / 8, 256>>>(x1, g2, be2, h);
    // FFN
    tf32_gemm_kernel<true, true, false><<<dim3(NTOK / 128, 12), 128, GEMM_SMEM>>>(h, w1, b1, nullptr, ff, DIM, FFDIM);
    tf32_gemm_kernel<false, true, true><<<dim3(NTOK / 128, 3), 128, GEMM_SMEM>>>(ff, w2, b2, x1, out, FFDIM, DIM);
}